// round 14
// baseline (speedup 1.0000x reference)
#include <cuda_runtime.h>
#include <cuda_fp16.h>
#include <cstdint>
#include <cstddef>

#define TT 64
#define BB 512
#define DD 512
#define HH 2048

// ---------------- scratch (device globals) ---------------------------------
__device__ __align__(16) float  g_ycur[BB * DD];
__device__ __align__(16) float  g_acc [BB * DD];
__device__ __align__(16) __half g_a   [BB * DD];          // gemm1 A operand
__device__ __align__(16) __half g_h   [(size_t)BB * HH];  // hidden activations
__device__ __align__(16) __half g_W1h [(size_t)DD * HH];
__device__ __align__(16) __half g_W2h [(size_t)HH * DD];
__device__ __align__(16) float  g_p2[8][(size_t)BB * DD]; // gemm2 split-K partials
__device__ int g_cnt2[64];       // per gemm2 tile arrival counter

// ---------------- ptx helpers ----------------------------------------------
__device__ __forceinline__ uint32_t su32(const void* p) {
    return (uint32_t)__cvta_generic_to_shared(p);
}
#define CPA16(d, s) asm volatile("cp.async.cg.shared.global [%0], [%1], 16;" :: "r"(d), "l"(s))
#define CPC()       asm volatile("cp.async.commit_group;" ::: "memory")
#define WAITG(n)    asm volatile("cp.async.wait_group %0;" :: "n"(n) : "memory")

__device__ __forceinline__ void ldsm_x4(uint32_t a[4], uint32_t addr) {
    asm volatile("ldmatrix.sync.aligned.m8n8.x4.shared.b16 {%0,%1,%2,%3}, [%4];"
                 : "=r"(a[0]), "=r"(a[1]), "=r"(a[2]), "=r"(a[3]) : "r"(addr));
}
__device__ __forceinline__ void ldsm_x4_t(uint32_t a[4], uint32_t addr) {
    asm volatile("ldmatrix.sync.aligned.m8n8.x4.trans.shared.b16 {%0,%1,%2,%3}, [%4];"
                 : "=r"(a[0]), "=r"(a[1]), "=r"(a[2]), "=r"(a[3]) : "r"(addr));
}
__device__ __forceinline__ void mma_fp16(float c[4], const uint32_t a[4],
                                         uint32_t b0, uint32_t b1) {
    asm volatile(
        "mma.sync.aligned.m16n8k16.row.col.f32.f16.f16.f32 "
        "{%0,%1,%2,%3},{%4,%5,%6,%7},{%8,%9},{%0,%1,%2,%3};"
        : "+f"(c[0]), "+f"(c[1]), "+f"(c[2]), "+f"(c[3])
        : "r"(a[0]), "r"(a[1]), "r"(a[2]), "r"(a[3]), "r"(b0), "r"(b1));
}

// ---------------- init / convert -------------------------------------------
__global__ void init_state(const float* __restrict__ y0, float* __restrict__ out) {
    int idx = blockIdx.x * blockDim.x + threadIdx.x;
    float4 v = ((const float4*)y0)[idx];
    ((float4*)out)[idx] = v;
    ((float4*)g_ycur)[idx] = v;
    __half2* a2 = (__half2*)g_a;
    a2[idx * 2]     = __floats2half2_rn(v.x, v.y);
    a2[idx * 2 + 1] = __floats2half2_rn(v.z, v.w);
    if (blockIdx.x == 0 && threadIdx.x < 64) g_cnt2[threadIdx.x] = 0;
}
__global__ void convert_w(const float* __restrict__ src, __half* __restrict__ dst) {
    int idx = blockIdx.x * blockDim.x + threadIdx.x;
    float4 v = ((const float4*)src)[idx];
    __half2* d2 = (__half2*)dst;
    d2[idx * 2]     = __floats2half2_rn(v.x, v.y);
    d2[idx * 2 + 1] = __floats2half2_rn(v.z, v.w);
}

extern __shared__ char dyn_sm[];

// ============================================================================
// GEMM1: g_h = tanh(g_a[512x512] @ W1[512x2048] + b1)
// CTA 64x128, 512 thr = 16 warps = 2 k-groups x (2m x 4n), warp tile 32x32.
// Intra-CTA split-K=2 (each k-group owns K=256), shared BK=128 3-stage
// pipeline, smem reduction kg1 -> kg0, tanh epilogue by kg0.
// Grid (16, 8) = 128 CTAs.
// ============================================================================
#define A1PIT 136        // A smem pitch (halves): 128 + 8
#define B1PIT 136        // B smem pitch (halves): 128 + 8
#define ABY1 (64 * A1PIT * 2)             // 17408
#define STG1 (ABY1 + 128 * B1PIT * 2)     // 17408 + 34816 = 52224
#define SMEM1 (3 * STG1)                  // 156672
#define NT1 4
#define RPIT 132         // reduction buffer pitch (floats)

__global__ void __launch_bounds__(512, 1) gemm1_kernel(const float* __restrict__ b1) {
    const int tid = threadIdx.x, lane = tid & 31, warp = tid >> 5;
    const int g = lane >> 2, tg = lane & 3;
    const int kg = warp >> 3, w8 = warp & 7;
    const int wm = (w8 >> 2) * 32, wn = (w8 & 3) * 32;
    const int kofs = kg * 64;             // k-group offset within BK=128 stage
    const int bm = blockIdx.y * 64, bn = blockIdx.x * 128;
    const int l16 = lane & 15, h16 = (lane >> 4) * 8;

    auto loadStage = [&](int st, int kt) {
        char* Ab = dyn_sm + st * STG1;
        char* Bb = Ab + ABY1;
#pragma unroll
        for (int l = 0; l < 2; l++) {
            int j = tid + l * 512, r = j >> 4, c = (j & 15) * 8;
            CPA16(su32(Ab + (r * A1PIT + c) * 2),
                  g_a + (size_t)(bm + r) * DD + kt * 128 + c);
        }
#pragma unroll
        for (int l = 0; l < 4; l++) {
            int j = tid + l * 512, r = j >> 4, c = (j & 15) * 8;
            CPA16(su32(Bb + (r * B1PIT + c) * 2),
                  g_W1h + (size_t)(kt * 128 + r) * HH + bn + c);
        }
        CPC();
    };
    auto ldfA = [&](uint32_t Af[2][4], int st, int ks) {
        char* Ab = dyn_sm + st * STG1;
#pragma unroll
        for (int mi = 0; mi < 2; mi++)
            ldsm_x4(Af[mi], su32(Ab + ((wm + mi * 16 + l16) * A1PIT + ks + h16) * 2));
    };
    auto ldfB = [&](uint32_t Bf[4][2], int st, int ks) {
        char* Bb = dyn_sm + st * STG1 + ABY1;
#pragma unroll
        for (int bt = 0; bt < 2; bt++) {
            uint32_t r[4];
            ldsm_x4_t(r, su32(Bb + ((ks + l16) * B1PIT + wn + bt * 16 + h16) * 2));
            Bf[bt * 2][0] = r[0]; Bf[bt * 2][1] = r[1];
            Bf[bt * 2 + 1][0] = r[2]; Bf[bt * 2 + 1][1] = r[3];
        }
    };

    loadStage(0, 0); loadStage(1, 1); loadStage(2, 2);
    WAITG(2);
    __syncthreads();

    float acc[2][4][4];
#pragma unroll
    for (int mi = 0; mi < 2; mi++)
#pragma unroll
        for (int ni = 0; ni < 4; ni++)
#pragma unroll
            for (int r = 0; r < 4; r++) acc[mi][ni][r] = 0.f;

    uint32_t Af[2][2][4], Bf[2][4][2];
    ldfA(Af[0], 0, kofs); ldfB(Bf[0], 0, kofs);

    for (int kt = 0; kt < NT1; kt++) {
        const int st = kt % 3;
#pragma unroll
        for (int ks = 0; ks < 4; ks++) {
            const int pb = ks & 1;
            if (ks == 3) { WAITG(1); __syncthreads(); }
            const int nst = (ks < 3) ? st : ((kt + 1) % 3);
            const int nks = (ks < 3) ? (kofs + (ks + 1) * 16) : kofs;
            if (ks < 3 || kt + 1 < NT1) {
                ldfA(Af[pb ^ 1], nst, nks);
                ldfB(Bf[pb ^ 1], nst, nks);
            }
#pragma unroll
            for (int mi = 0; mi < 2; mi++)
#pragma unroll
                for (int ni = 0; ni < 4; ni++)
                    mma_fp16(acc[mi][ni], Af[pb][mi], Bf[pb][ni][0], Bf[pb][ni][1]);
        }
        if (kt + 3 < NT1) loadStage((kt + 3) % 3, kt + 3); else CPC();
    }

    // drain all cp.async before reusing smem as the reduction buffer
    WAITG(0);
    __syncthreads();

    float* red = (float*)dyn_sm;          // 64 x RPIT fp32 = 33792 B
    if (kg == 1) {
#pragma unroll
        for (int mi = 0; mi < 2; mi++)
#pragma unroll
            for (int ni = 0; ni < 4; ni++) {
                int col = wn + ni * 8 + tg * 2;
#pragma unroll
                for (int hr = 0; hr < 2; hr++) {
                    int row = wm + mi * 16 + g + hr * 8;
                    *(float2*)&red[row * RPIT + col] =
                        make_float2(acc[mi][ni][hr * 2 + 0], acc[mi][ni][hr * 2 + 1]);
                }
            }
    }
    __syncthreads();
    if (kg == 0) {
        // combine (kg0 + kg1, fixed order -> deterministic) + tanh epilogue
#pragma unroll
        for (int mi = 0; mi < 2; mi++)
#pragma unroll
            for (int ni = 0; ni < 4; ni++) {
                int coll = wn + ni * 8 + tg * 2;
                int col = bn + coll;
                float bc0 = __ldg(b1 + col), bc1 = __ldg(b1 + col + 1);
#pragma unroll
                for (int hr = 0; hr < 2; hr++) {
                    int rowl = wm + mi * 16 + g + hr * 8;
                    int row = bm + rowl;
                    float2 p = *(const float2*)&red[rowl * RPIT + coll];
                    float v0 = tanhf(acc[mi][ni][hr * 2 + 0] + p.x + bc0);
                    float v1 = tanhf(acc[mi][ni][hr * 2 + 1] + p.y + bc1);
                    *(__half2*)&g_h[(size_t)row * HH + col] = __floats2half2_rn(v0, v1);
                }
            }
    }
}

// ============================================================================
// GEMM2 (R11/R13 shape, unchanged): C = g_h[512x2048] @ W2[2048x512];
// split-K=8 (K=256/CTA).  CTA 64x64, 128 thr, warps 2x2 (wt 32x32), BK=32,
// 3-stage.  Grid (8, 8, 8) = 512 CTAs.  Last arriver sums 8 partials in
// fixed kz order (deterministic) + RK4 epilogue.
// ============================================================================
#define A2PIT 40                        // 32 + 8
#define B2PIT 72                        // 64 + 8
#define ABY2 (64 * A2PIT * 2)           // 5120 B
#define BBY2 (32 * B2PIT * 2)           // 4608 B
#define STG2 (ABY2 + BBY2)              // 9728 B
#define SMEM2 (3 * STG2)                // 29184 B
#define NT2 8

__global__ void __launch_bounds__(128, 4) gemm2_kernel(const float* __restrict__ b2,
                                                       const float* __restrict__ tarr,
                                                       float* __restrict__ out,
                                                       int s, float wgt, float cnext,
                                                       int first, int last) {
    const int bm = blockIdx.y * 64, bn = blockIdx.x * 64, kz = blockIdx.z;
    const int tile = blockIdx.y * 8 + blockIdx.x;
    const int tid = threadIdx.x, lane = tid & 31, warp = tid >> 5;
    const int g = lane >> 2, tg = lane & 3;
    const int wm = (warp >> 1) * 32, wn = (warp & 1) * 32;
    const int l16 = lane & 15, h16 = (lane >> 4) * 8;

    const __half* Ag = g_h + (size_t)bm * HH + kz * 256;
    const __half* Bg = g_W2h + (size_t)(kz * 256) * DD + bn;

    auto loadStage = [&](int st, int kt) {
        char* Ab = dyn_sm + st * STG2;
        char* Bb = Ab + ABY2;
#pragma unroll
        for (int l = 0; l < 2; l++) {
            int j = tid + l * 128, r = j >> 2, c = (j & 3) * 8;
            CPA16(su32(Ab + (r * A2PIT + c) * 2), Ag + (size_t)r * HH + kt * 32 + c);
        }
#pragma unroll
        for (int l = 0; l < 2; l++) {
            int j = tid + l * 128, r = j >> 3, c = (j & 7) * 8;
            CPA16(su32(Bb + (r * B2PIT + c) * 2), Bg + (size_t)(kt * 32 + r) * DD + c);
        }
        CPC();
    };
    auto ldfA = [&](uint32_t Af[2][4], int st, int ks) {
        char* Ab = dyn_sm + st * STG2;
#pragma unroll
        for (int mi = 0; mi < 2; mi++)
            ldsm_x4(Af[mi], su32(Ab + ((wm + mi * 16 + l16) * A2PIT + ks + h16) * 2));
    };
    auto ldfB = [&](uint32_t Bf[4][2], int st, int ks) {
        char* Bb = dyn_sm + st * STG2 + ABY2;
#pragma unroll
        for (int bt = 0; bt < 2; bt++) {
            uint32_t r[4];
            ldsm_x4_t(r, su32(Bb + ((ks + l16) * B2PIT + wn + bt * 16 + h16) * 2));
            Bf[bt * 2][0] = r[0]; Bf[bt * 2][1] = r[1];
            Bf[bt * 2 + 1][0] = r[2]; Bf[bt * 2 + 1][1] = r[3];
        }
    };

    loadStage(0, 0); loadStage(1, 1); loadStage(2, 2);
    WAITG(2);
    __syncthreads();

    float acc[2][4][4];
#pragma unroll
    for (int mi = 0; mi < 2; mi++)
#pragma unroll
        for (int ni = 0; ni < 4; ni++)
#pragma unroll
            for (int r = 0; r < 4; r++) acc[mi][ni][r] = 0.f;

    uint32_t Af[2][2][4], Bf[2][4][2];
    ldfA(Af[0], 0, 0); ldfB(Bf[0], 0, 0);

    for (int kt = 0; kt < NT2; kt++) {
        const int st = kt % 3;
#pragma unroll
        for (int ks = 0; ks < 2; ks++) {
            const int pb = ks & 1;
            if (ks == 1) { WAITG(1); __syncthreads(); }
            const int nst = (ks == 0) ? st : ((kt + 1) % 3);
            const int nks = (ks == 0) ? 16 : 0;
            if (ks == 0 || kt + 1 < NT2) {
                ldfA(Af[pb ^ 1], nst, nks);
                ldfB(Bf[pb ^ 1], nst, nks);
            }
#pragma unroll
            for (int mi = 0; mi < 2; mi++)
#pragma unroll
                for (int ni = 0; ni < 4; ni++)
                    mma_fp16(acc[mi][ni], Af[pb][mi], Bf[pb][ni][0], Bf[pb][ni][1]);
        }
        if (kt + 3 < NT2) loadStage((kt + 3) % 3, kt + 3); else CPC();
    }

    // publish partial
    {
        float* dst = g_p2[kz];
#pragma unroll
        for (int mi = 0; mi < 2; mi++)
#pragma unroll
            for (int ni = 0; ni < 4; ni++) {
                int col = bn + wn + ni * 8 + tg * 2;
#pragma unroll
                for (int hr = 0; hr < 2; hr++) {
                    int row = bm + wm + mi * 16 + g + hr * 8;
                    *(float2*)&dst[(size_t)row * DD + col] =
                        make_float2(acc[mi][ni][hr * 2 + 0], acc[mi][ni][hr * 2 + 1]);
                }
            }
    }

    // last-arriver reduction (threadFenceReduction; self-resetting counter)
    {
        __shared__ int s_last;
        __syncthreads();
        if (tid == 0) {
            __threadfence();
            int old = atomicAdd(&g_cnt2[tile], 1);
            s_last = (old == 7);
            if (s_last) atomicExch(&g_cnt2[tile], 0);
        }
        __syncthreads();
        if (!s_last) return;
        if (tid == 0) __threadfence();
        __syncthreads();
    }

    // combine + RK4 epilogue (128 thr x 32 elems over the 64x64 tile)
    const float inv6 = 1.0f / 6.0f;
#pragma unroll
    for (int q = 0; q < 4; q++) {
        int row = bm + (tid >> 3) + q * 16;
        int col = bn + (tid & 7) * 8;
        size_t off = (size_t)row * DD + col;
        float dt = __ldg(tarr + (size_t)(s + 1) * BB + row)
                 - __ldg(tarr + (size_t)s * BB + row);

        float sum[8];
        {
            float4 a = *(const float4*)&g_p2[0][off];
            float4 b = *(const float4*)&g_p2[0][off + 4];
            sum[0] = a.x; sum[1] = a.y; sum[2] = a.z; sum[3] = a.w;
            sum[4] = b.x; sum[5] = b.y; sum[6] = b.z; sum[7] = b.w;
        }
#pragma unroll
        for (int z = 1; z < 8; z++) {
            float4 a = *(const float4*)&g_p2[z][off];
            float4 b = *(const float4*)&g_p2[z][off + 4];
            sum[0] += a.x; sum[1] += a.y; sum[2] += a.z; sum[3] += a.w;
            sum[4] += b.x; sum[5] += b.y; sum[6] += b.z; sum[7] += b.w;
        }

        float kv[8];
#pragma unroll
        for (int e = 0; e < 8; e++)
            kv[e] = dt * (sum[e] + __ldg(b2 + col + e));

        float yc[8], av[8];
        *(float4*)&yc[0] = *(const float4*)&g_ycur[off];
        *(float4*)&yc[4] = *(const float4*)&g_ycur[off + 4];
        if (first) {
#pragma unroll
            for (int e = 0; e < 8; e++) av[e] = wgt * kv[e];
        } else {
            *(float4*)&av[0] = *(const float4*)&g_acc[off];
            *(float4*)&av[4] = *(const float4*)&g_acc[off + 4];
#pragma unroll
            for (int e = 0; e < 8; e++) av[e] += wgt * kv[e];
        }

        uint4 ah;
        if (!last) {
            *(float4*)&g_acc[off]     = *(const float4*)&av[0];
            *(float4*)&g_acc[off + 4] = *(const float4*)&av[4];
            __half2 h;
            h = __floats2half2_rn(yc[0] + cnext * kv[0], yc[1] + cnext * kv[1]);
            __builtin_memcpy(&ah.x, &h, 4);
            h = __floats2half2_rn(yc[2] + cnext * kv[2], yc[3] + cnext * kv[3]);
            __builtin_memcpy(&ah.y, &h, 4);
            h = __floats2half2_rn(yc[4] + cnext * kv[4], yc[5] + cnext * kv[5]);
            __builtin_memcpy(&ah.z, &h, 4);
            h = __floats2half2_rn(yc[6] + cnext * kv[6], yc[7] + cnext * kv[7]);
            __builtin_memcpy(&ah.w, &h, 4);
        } else {
            float yn[8];
#pragma unroll
            for (int e = 0; e < 8; e++) yn[e] = yc[e] + av[e] * inv6;
            *(float4*)&g_ycur[off]     = *(const float4*)&yn[0];
            *(float4*)&g_ycur[off + 4] = *(const float4*)&yn[4];
            *(float4*)&out[(size_t)(s + 1) * BB * DD + off]     = *(const float4*)&yn[0];
            *(float4*)&out[(size_t)(s + 1) * BB * DD + off + 4] = *(const float4*)&yn[4];
            __half2 h;
            h = __floats2half2_rn(yn[0], yn[1]); __builtin_memcpy(&ah.x, &h, 4);
            h = __floats2half2_rn(yn[2], yn[3]); __builtin_memcpy(&ah.y, &h, 4);
            h = __floats2half2_rn(yn[4], yn[5]); __builtin_memcpy(&ah.z, &h, 4);
            h = __floats2half2_rn(yn[6], yn[7]); __builtin_memcpy(&ah.w, &h, 4);
        }
        *(uint4*)&g_a[off] = ah;
    }
}

// ---------------------------------------------------------------------------
extern "C" void kernel_launch(void* const* d_in, const int* in_sizes, int n_in,
                              void* d_out, int out_size) {
    const float* y0 = (const float*)d_in[0];
    const float* t  = (const float*)d_in[1];
    const float* W1 = (const float*)d_in[2];
    const float* b1 = (const float*)d_in[3];
    const float* W2 = (const float*)d_in[4];
    const float* b2 = (const float*)d_in[5];
    float* out = (float*)d_out;

    cudaFuncSetAttribute(gemm1_kernel, cudaFuncAttributeMaxDynamicSharedMemorySize, SMEM1);
    cudaFuncSetAttribute(gemm2_kernel, cudaFuncAttributeMaxDynamicSharedMemorySize, SMEM2);

    __half* w1h; cudaGetSymbolAddress((void**)&w1h, g_W1h);
    __half* w2h; cudaGetSymbolAddress((void**)&w2h, g_W2h);

    init_state<<<(BB * DD / 4) / 256, 256>>>(y0, out);
    convert_w<<<(DD * HH / 4) / 256, 256>>>(W1, w1h);
    convert_w<<<(HH * DD / 4) / 256, 256>>>(W2, w2h);

    const float ws[4] = {1.0f, 2.0f, 2.0f, 1.0f};
    const float cn[4] = {0.5f, 0.5f, 1.0f, 0.0f};

    dim3 grid1(HH / 128, BB / 64);     // 16 x 8 = 128 CTAs
    dim3 grid2(DD / 64, BB / 64, 8);   // 8 x 8 x 8 = 512 CTAs

    for (int s = 0; s < TT - 1; ++s) {
        for (int i = 0; i < 4; ++i) {
            gemm1_kernel<<<grid1, 512, SMEM1>>>(b1);
            gemm2_kernel<<<grid2, 128, SMEM2>>>(b2, t, out, s, ws[i], cn[i],
                                                (i == 0) ? 1 : 0, (i == 3) ? 1 : 0);
        }
    }
}

// round 15
// speedup vs baseline: 1.1030x; 1.1030x over previous
#include <cuda_runtime.h>
#include <cuda_fp16.h>
#include <cstdint>
#include <cstddef>

#define TT 64
#define BB 512
#define DD 512
#define HH 2048

// ---------------- scratch (device globals) ---------------------------------
__device__ __align__(16) float  g_ycur[BB * DD];
__device__ __align__(16) float  g_acc [BB * DD];
__device__ __align__(16) __half g_a   [BB * DD];          // gemm1 A operand
__device__ __align__(16) __half g_h   [(size_t)BB * HH];  // hidden activations
__device__ __align__(16) __half g_W1h [(size_t)DD * HH];
__device__ __align__(16) __half g_W2h [(size_t)HH * DD];
__device__ __align__(16) float  g_p2[8][(size_t)BB * DD]; // gemm2 split-K partials
__device__ int g_cnt2[64];       // per gemm2 tile arrival counter

// ---------------- ptx helpers ----------------------------------------------
__device__ __forceinline__ uint32_t su32(const void* p) {
    return (uint32_t)__cvta_generic_to_shared(p);
}
#define CPA16(d, s) asm volatile("cp.async.cg.shared.global [%0], [%1], 16;" :: "r"(d), "l"(s))
#define CPC()       asm volatile("cp.async.commit_group;" ::: "memory")
#define WAITG(n)    asm volatile("cp.async.wait_group %0;" :: "n"(n) : "memory")

__device__ __forceinline__ void ldsm_x4(uint32_t a[4], uint32_t addr) {
    asm volatile("ldmatrix.sync.aligned.m8n8.x4.shared.b16 {%0,%1,%2,%3}, [%4];"
                 : "=r"(a[0]), "=r"(a[1]), "=r"(a[2]), "=r"(a[3]) : "r"(addr));
}
__device__ __forceinline__ void ldsm_x4_t(uint32_t a[4], uint32_t addr) {
    asm volatile("ldmatrix.sync.aligned.m8n8.x4.trans.shared.b16 {%0,%1,%2,%3}, [%4];"
                 : "=r"(a[0]), "=r"(a[1]), "=r"(a[2]), "=r"(a[3]) : "r"(addr));
}
__device__ __forceinline__ void mma_fp16(float c[4], const uint32_t a[4],
                                         uint32_t b0, uint32_t b1) {
    asm volatile(
        "mma.sync.aligned.m16n8k16.row.col.f32.f16.f16.f32 "
        "{%0,%1,%2,%3},{%4,%5,%6,%7},{%8,%9},{%0,%1,%2,%3};"
        : "+f"(c[0]), "+f"(c[1]), "+f"(c[2]), "+f"(c[3])
        : "r"(a[0]), "r"(a[1]), "r"(a[2]), "r"(a[3]), "r"(b0), "r"(b1));
}

// ---------------- init / convert -------------------------------------------
__global__ void init_state(const float* __restrict__ y0, float* __restrict__ out) {
    int idx = blockIdx.x * blockDim.x + threadIdx.x;
    float4 v = ((const float4*)y0)[idx];
    ((float4*)out)[idx] = v;
    ((float4*)g_ycur)[idx] = v;
    __half2* a2 = (__half2*)g_a;
    a2[idx * 2]     = __floats2half2_rn(v.x, v.y);
    a2[idx * 2 + 1] = __floats2half2_rn(v.z, v.w);
    if (blockIdx.x == 0 && threadIdx.x < 64) g_cnt2[threadIdx.x] = 0;
}
__global__ void convert_w(const float* __restrict__ src, __half* __restrict__ dst) {
    int idx = blockIdx.x * blockDim.x + threadIdx.x;
    float4 v = ((const float4*)src)[idx];
    __half2* d2 = (__half2*)dst;
    d2[idx * 2]     = __floats2half2_rn(v.x, v.y);
    d2[idx * 2 + 1] = __floats2half2_rn(v.z, v.w);
}

extern __shared__ char dyn_sm[];

// ============================================================================
// GEMM1: g_h = tanh(g_a[512x512] @ W1[512x2048] + b1)
// CTA 64x128, 512 thr = 16 warps = 2 k-groups x (2m x 4n), warp tile 32x32.
// Intra-CTA split-K=2, BK=128, 3-stage.  PDL: W1 prologue before
// gridDependencySynchronize, A (g_a, produced by prev gemm2) after.
// Grid (16, 8) = 128 CTAs.
// ============================================================================
#define A1PIT 136
#define B1PIT 136
#define ABY1 (64 * A1PIT * 2)             // 17408
#define STG1 (ABY1 + 128 * B1PIT * 2)     // 52224
#define SMEM1 (3 * STG1)                  // 156672
#define NT1 4
#define RPIT 132

__global__ void __launch_bounds__(512, 1) gemm1_kernel(const float* __restrict__ b1) {
    const int tid = threadIdx.x, lane = tid & 31, warp = tid >> 5;
    const int g = lane >> 2, tg = lane & 3;
    const int kg = warp >> 3, w8 = warp & 7;
    const int wm = (w8 >> 2) * 32, wn = (w8 & 3) * 32;
    const int kofs = kg * 64;
    const int bm = blockIdx.y * 64, bn = blockIdx.x * 128;
    const int l16 = lane & 15, h16 = (lane >> 4) * 8;

    auto loadA = [&](int st, int kt) {
        char* Ab = dyn_sm + st * STG1;
#pragma unroll
        for (int l = 0; l < 2; l++) {
            int j = tid + l * 512, r = j >> 4, c = (j & 15) * 8;
            CPA16(su32(Ab + (r * A1PIT + c) * 2),
                  g_a + (size_t)(bm + r) * DD + kt * 128 + c);
        }
    };
    auto loadB = [&](int st, int kt) {
        char* Bb = dyn_sm + st * STG1 + ABY1;
#pragma unroll
        for (int l = 0; l < 4; l++) {
            int j = tid + l * 512, r = j >> 4, c = (j & 15) * 8;
            CPA16(su32(Bb + (r * B1PIT + c) * 2),
                  g_W1h + (size_t)(kt * 128 + r) * HH + bn + c);
        }
    };
    auto loadStage = [&](int st, int kt) { loadA(st, kt); loadB(st, kt); CPC(); };
    auto ldfA = [&](uint32_t Af[2][4], int st, int ks) {
        char* Ab = dyn_sm + st * STG1;
#pragma unroll
        for (int mi = 0; mi < 2; mi++)
            ldsm_x4(Af[mi], su32(Ab + ((wm + mi * 16 + l16) * A1PIT + ks + h16) * 2));
    };
    auto ldfB = [&](uint32_t Bf[4][2], int st, int ks) {
        char* Bb = dyn_sm + st * STG1 + ABY1;
#pragma unroll
        for (int bt = 0; bt < 2; bt++) {
            uint32_t r[4];
            ldsm_x4_t(r, su32(Bb + ((ks + l16) * B1PIT + wn + bt * 16 + h16) * 2));
            Bf[bt * 2][0] = r[0]; Bf[bt * 2][1] = r[1];
            Bf[bt * 2 + 1][0] = r[2]; Bf[bt * 2 + 1][1] = r[3];
        }
    };

    // PDL prologue: weights first (independent of producer kernel) ...
    loadB(0, 0); loadB(1, 1); loadB(2, 2);
    // ... then wait for producer (prev gemm2 wrote g_a) and load A.
    cudaGridDependencySynchronize();
    loadA(0, 0); CPC();                 // group0 = {B0,B1,B2,A0}
    loadA(1, 1); CPC();                 // group1 = {A1}
    loadA(2, 2); CPC();                 // group2 = {A2}
    WAITG(2);
    __syncthreads();

    float acc[2][4][4];
#pragma unroll
    for (int mi = 0; mi < 2; mi++)
#pragma unroll
        for (int ni = 0; ni < 4; ni++)
#pragma unroll
            for (int r = 0; r < 4; r++) acc[mi][ni][r] = 0.f;

    uint32_t Af[2][2][4], Bf[2][4][2];
    ldfA(Af[0], 0, kofs); ldfB(Bf[0], 0, kofs);

    for (int kt = 0; kt < NT1; kt++) {
        const int st = kt % 3;
#pragma unroll
        for (int ks = 0; ks < 4; ks++) {
            const int pb = ks & 1;
            if (ks == 3) { WAITG(1); __syncthreads(); }
            const int nst = (ks < 3) ? st : ((kt + 1) % 3);
            const int nks = (ks < 3) ? (kofs + (ks + 1) * 16) : kofs;
            if (ks < 3 || kt + 1 < NT1) {
                ldfA(Af[pb ^ 1], nst, nks);
                ldfB(Bf[pb ^ 1], nst, nks);
            }
#pragma unroll
            for (int mi = 0; mi < 2; mi++)
#pragma unroll
                for (int ni = 0; ni < 4; ni++)
                    mma_fp16(acc[mi][ni], Af[pb][mi], Bf[pb][ni][0], Bf[pb][ni][1]);
        }
        if (kt + 3 < NT1) loadStage((kt + 3) % 3, kt + 3); else CPC();
    }

    // allow next kernel (gemm2) to start its W2 prologue
    cudaTriggerProgrammaticLaunchCompletion();

    // drain cp.async before reusing smem as reduction buffer
    WAITG(0);
    __syncthreads();

    float* red = (float*)dyn_sm;
    if (kg == 1) {
#pragma unroll
        for (int mi = 0; mi < 2; mi++)
#pragma unroll
            for (int ni = 0; ni < 4; ni++) {
                int col = wn + ni * 8 + tg * 2;
#pragma unroll
                for (int hr = 0; hr < 2; hr++) {
                    int row = wm + mi * 16 + g + hr * 8;
                    *(float2*)&red[row * RPIT + col] =
                        make_float2(acc[mi][ni][hr * 2 + 0], acc[mi][ni][hr * 2 + 1]);
                }
            }
    }
    __syncthreads();
    if (kg == 0) {
#pragma unroll
        for (int mi = 0; mi < 2; mi++)
#pragma unroll
            for (int ni = 0; ni < 4; ni++) {
                int coll = wn + ni * 8 + tg * 2;
                int col = bn + coll;
                float bc0 = __ldg(b1 + col), bc1 = __ldg(b1 + col + 1);
#pragma unroll
                for (int hr = 0; hr < 2; hr++) {
                    int rowl = wm + mi * 16 + g + hr * 8;
                    int row = bm + rowl;
                    float2 p = *(const float2*)&red[rowl * RPIT + coll];
                    float v0 = tanhf(acc[mi][ni][hr * 2 + 0] + p.x + bc0);
                    float v1 = tanhf(acc[mi][ni][hr * 2 + 1] + p.y + bc1);
                    *(__half2*)&g_h[(size_t)row * HH + col] = __floats2half2_rn(v0, v1);
                }
            }
    }
}

// ============================================================================
// GEMM2: C = g_h[512x2048] @ W2[2048x512]; split-K=8 (K=256/CTA).
// CTA 64x64, 128 thr, warps 2x2 (wt 32x32), BK=32, 3-stage.
// PDL: W2 prologue before gridDependencySynchronize, A (g_h) after.
// Grid (8, 8, 8) = 512 CTAs.  Last arriver: fixed-order combine + RK4.
// ============================================================================
#define A2PIT 40
#define B2PIT 72
#define ABY2 (64 * A2PIT * 2)           // 5120 B
#define BBY2 (32 * B2PIT * 2)           // 4608 B
#define STG2 (ABY2 + BBY2)              // 9728 B
#define SMEM2 (3 * STG2)                // 29184 B
#define NT2 8

__global__ void __launch_bounds__(128, 4) gemm2_kernel(const float* __restrict__ b2,
                                                       const float* __restrict__ tarr,
                                                       float* __restrict__ out,
                                                       int s, float wgt, float cnext,
                                                       int first, int last) {
    const int bm = blockIdx.y * 64, bn = blockIdx.x * 64, kz = blockIdx.z;
    const int tile = blockIdx.y * 8 + blockIdx.x;
    const int tid = threadIdx.x, lane = tid & 31, warp = tid >> 5;
    const int g = lane >> 2, tg = lane & 3;
    const int wm = (warp >> 1) * 32, wn = (warp & 1) * 32;
    const int l16 = lane & 15, h16 = (lane >> 4) * 8;

    const __half* Ag = g_h + (size_t)bm * HH + kz * 256;
    const __half* Bg = g_W2h + (size_t)(kz * 256) * DD + bn;

    auto loadA = [&](int st, int kt) {
        char* Ab = dyn_sm + st * STG2;
#pragma unroll
        for (int l = 0; l < 2; l++) {
            int j = tid + l * 128, r = j >> 2, c = (j & 3) * 8;
            CPA16(su32(Ab + (r * A2PIT + c) * 2), Ag + (size_t)r * HH + kt * 32 + c);
        }
    };
    auto loadB = [&](int st, int kt) {
        char* Bb = dyn_sm + st * STG2 + ABY2;
#pragma unroll
        for (int l = 0; l < 2; l++) {
            int j = tid + l * 128, r = j >> 3, c = (j & 7) * 8;
            CPA16(su32(Bb + (r * B2PIT + c) * 2), Bg + (size_t)(kt * 32 + r) * DD + c);
        }
    };
    auto loadStage = [&](int st, int kt) { loadA(st, kt); loadB(st, kt); CPC(); };
    auto ldfA = [&](uint32_t Af[2][4], int st, int ks) {
        char* Ab = dyn_sm + st * STG2;
#pragma unroll
        for (int mi = 0; mi < 2; mi++)
            ldsm_x4(Af[mi], su32(Ab + ((wm + mi * 16 + l16) * A2PIT + ks + h16) * 2));
    };
    auto ldfB = [&](uint32_t Bf[4][2], int st, int ks) {
        char* Bb = dyn_sm + st * STG2 + ABY2;
#pragma unroll
        for (int bt = 0; bt < 2; bt++) {
            uint32_t r[4];
            ldsm_x4_t(r, su32(Bb + ((ks + l16) * B2PIT + wn + bt * 16 + h16) * 2));
            Bf[bt * 2][0] = r[0]; Bf[bt * 2][1] = r[1];
            Bf[bt * 2 + 1][0] = r[2]; Bf[bt * 2 + 1][1] = r[3];
        }
    };

    // PDL prologue: weights first, A (g_h from gemm1) after the dependency.
    loadB(0, 0); loadB(1, 1); loadB(2, 2);
    cudaGridDependencySynchronize();
    loadA(0, 0); CPC();
    loadA(1, 1); CPC();
    loadA(2, 2); CPC();
    WAITG(2);
    __syncthreads();

    float acc[2][4][4];
#pragma unroll
    for (int mi = 0; mi < 2; mi++)
#pragma unroll
        for (int ni = 0; ni < 4; ni++)
#pragma unroll
            for (int r = 0; r < 4; r++) acc[mi][ni][r] = 0.f;

    uint32_t Af[2][2][4], Bf[2][4][2];
    ldfA(Af[0], 0, 0); ldfB(Bf[0], 0, 0);

    for (int kt = 0; kt < NT2; kt++) {
        const int st = kt % 3;
#pragma unroll
        for (int ks = 0; ks < 2; ks++) {
            const int pb = ks & 1;
            if (ks == 1) { WAITG(1); __syncthreads(); }
            const int nst = (ks == 0) ? st : ((kt + 1) % 3);
            const int nks = (ks == 0) ? 16 : 0;
            if (ks == 0 || kt + 1 < NT2) {
                ldfA(Af[pb ^ 1], nst, nks);
                ldfB(Bf[pb ^ 1], nst, nks);
            }
#pragma unroll
            for (int mi = 0; mi < 2; mi++)
#pragma unroll
                for (int ni = 0; ni < 4; ni++)
                    mma_fp16(acc[mi][ni], Af[pb][mi], Bf[pb][ni][0], Bf[pb][ni][1]);
        }
        if (kt + 3 < NT2) loadStage((kt + 3) % 3, kt + 3); else CPC();
    }

    // allow next kernel (gemm1 of next substage) to start its W1 prologue
    cudaTriggerProgrammaticLaunchCompletion();

    // publish partial
    {
        float* dst = g_p2[kz];
#pragma unroll
        for (int mi = 0; mi < 2; mi++)
#pragma unroll
            for (int ni = 0; ni < 4; ni++) {
                int col = bn + wn + ni * 8 + tg * 2;
#pragma unroll
                for (int hr = 0; hr < 2; hr++) {
                    int row = bm + wm + mi * 16 + g + hr * 8;
                    *(float2*)&dst[(size_t)row * DD + col] =
                        make_float2(acc[mi][ni][hr * 2 + 0], acc[mi][ni][hr * 2 + 1]);
                }
            }
    }

    // last-arriver reduction (threadFenceReduction; self-resetting counter)
    {
        __shared__ int s_last;
        __syncthreads();
        if (tid == 0) {
            __threadfence();
            int old = atomicAdd(&g_cnt2[tile], 1);
            s_last = (old == 7);
            if (s_last) atomicExch(&g_cnt2[tile], 0);
        }
        __syncthreads();
        if (!s_last) return;
        if (tid == 0) __threadfence();
        __syncthreads();
    }

    // combine + RK4 epilogue (128 thr x 32 elems over the 64x64 tile)
    const float inv6 = 1.0f / 6.0f;
#pragma unroll
    for (int q = 0; q < 4; q++) {
        int row = bm + (tid >> 3) + q * 16;
        int col = bn + (tid & 7) * 8;
        size_t off = (size_t)row * DD + col;
        float dt = __ldg(tarr + (size_t)(s + 1) * BB + row)
                 - __ldg(tarr + (size_t)s * BB + row);

        float sum[8];
        {
            float4 a = *(const float4*)&g_p2[0][off];
            float4 b = *(const float4*)&g_p2[0][off + 4];
            sum[0] = a.x; sum[1] = a.y; sum[2] = a.z; sum[3] = a.w;
            sum[4] = b.x; sum[5] = b.y; sum[6] = b.z; sum[7] = b.w;
        }
#pragma unroll
        for (int z = 1; z < 8; z++) {
            float4 a = *(const float4*)&g_p2[z][off];
            float4 b = *(const float4*)&g_p2[z][off + 4];
            sum[0] += a.x; sum[1] += a.y; sum[2] += a.z; sum[3] += a.w;
            sum[4] += b.x; sum[5] += b.y; sum[6] += b.z; sum[7] += b.w;
        }

        float kv[8];
#pragma unroll
        for (int e = 0; e < 8; e++)
            kv[e] = dt * (sum[e] + __ldg(b2 + col + e));

        float yc[8], av[8];
        *(float4*)&yc[0] = *(const float4*)&g_ycur[off];
        *(float4*)&yc[4] = *(const float4*)&g_ycur[off + 4];
        if (first) {
#pragma unroll
            for (int e = 0; e < 8; e++) av[e] = wgt * kv[e];
        } else {
            *(float4*)&av[0] = *(const float4*)&g_acc[off];
            *(float4*)&av[4] = *(const float4*)&g_acc[off + 4];
#pragma unroll
            for (int e = 0; e < 8; e++) av[e] += wgt * kv[e];
        }

        uint4 ah;
        if (!last) {
            *(float4*)&g_acc[off]     = *(const float4*)&av[0];
            *(float4*)&g_acc[off + 4] = *(const float4*)&av[4];
            __half2 h;
            h = __floats2half2_rn(yc[0] + cnext * kv[0], yc[1] + cnext * kv[1]);
            __builtin_memcpy(&ah.x, &h, 4);
            h = __floats2half2_rn(yc[2] + cnext * kv[2], yc[3] + cnext * kv[3]);
            __builtin_memcpy(&ah.y, &h, 4);
            h = __floats2half2_rn(yc[4] + cnext * kv[4], yc[5] + cnext * kv[5]);
            __builtin_memcpy(&ah.z, &h, 4);
            h = __floats2half2_rn(yc[6] + cnext * kv[6], yc[7] + cnext * kv[7]);
            __builtin_memcpy(&ah.w, &h, 4);
        } else {
            float yn[8];
#pragma unroll
            for (int e = 0; e < 8; e++) yn[e] = yc[e] + av[e] * inv6;
            *(float4*)&g_ycur[off]     = *(const float4*)&yn[0];
            *(float4*)&g_ycur[off + 4] = *(const float4*)&yn[4];
            *(float4*)&out[(size_t)(s + 1) * BB * DD + off]     = *(const float4*)&yn[0];
            *(float4*)&out[(size_t)(s + 1) * BB * DD + off + 4] = *(const float4*)&yn[4];
            __half2 h;
            h = __floats2half2_rn(yn[0], yn[1]); __builtin_memcpy(&ah.x, &h, 4);
            h = __floats2half2_rn(yn[2], yn[3]); __builtin_memcpy(&ah.y, &h, 4);
            h = __floats2half2_rn(yn[4], yn[5]); __builtin_memcpy(&ah.z, &h, 4);
            h = __floats2half2_rn(yn[6], yn[7]); __builtin_memcpy(&ah.w, &h, 4);
        }
        *(uint4*)&g_a[off] = ah;
    }
}

// ---------------------------------------------------------------------------
extern "C" void kernel_launch(void* const* d_in, const int* in_sizes, int n_in,
                              void* d_out, int out_size) {
    const float* y0 = (const float*)d_in[0];
    const float* t  = (const float*)d_in[1];
    const float* W1 = (const float*)d_in[2];
    const float* b1 = (const float*)d_in[3];
    const float* W2 = (const float*)d_in[4];
    const float* b2 = (const float*)d_in[5];
    float* out = (float*)d_out;

    cudaFuncSetAttribute(gemm1_kernel, cudaFuncAttributeMaxDynamicSharedMemorySize, SMEM1);
    cudaFuncSetAttribute(gemm2_kernel, cudaFuncAttributeMaxDynamicSharedMemorySize, SMEM2);

    __half* w1h; cudaGetSymbolAddress((void**)&w1h, g_W1h);
    __half* w2h; cudaGetSymbolAddress((void**)&w2h, g_W2h);

    init_state<<<(BB * DD / 4) / 256, 256>>>(y0, out);
    convert_w<<<(DD * HH / 4) / 256, 256>>>(W1, w1h);
    convert_w<<<(HH * DD / 4) / 256, 256>>>(W2, w2h);

    const float ws[4] = {1.0f, 2.0f, 2.0f, 1.0f};
    const float cn[4] = {0.5f, 0.5f, 1.0f, 0.0f};

    dim3 grid1(HH / 128, BB / 64);     // 16 x 8 = 128 CTAs
    dim3 grid2(DD / 64, BB / 64, 8);   // 8 x 8 x 8 = 512 CTAs

    cudaLaunchAttribute pdl[1];
    pdl[0].id = cudaLaunchAttributeProgrammaticStreamSerialization;
    pdl[0].val.programmaticStreamSerializationAllowed = 1;

    cudaLaunchConfig_t cfg1 = {};
    cfg1.gridDim = grid1; cfg1.blockDim = dim3(512, 1, 1);
    cfg1.dynamicSmemBytes = SMEM1;
    cfg1.attrs = pdl; cfg1.numAttrs = 1;

    cudaLaunchConfig_t cfg2 = {};
    cfg2.gridDim = grid2; cfg2.blockDim = dim3(128, 1, 1);
    cfg2.dynamicSmemBytes = SMEM2;
    cfg2.attrs = pdl; cfg2.numAttrs = 1;

    for (int s = 0; s < TT - 1; ++s) {
        for (int i = 0; i < 4; ++i) {
            if (s == 0 && i == 0) {
                // first gemm1: producer is convert_w (writes W1h, read in the
                // pre-dependency prologue) -> launch fully serialized.
                gemm1_kernel<<<grid1, 512, SMEM1>>>(b1);
            } else {
                cudaLaunchKernelEx(&cfg1, gemm1_kernel, b1);
            }
            cudaLaunchKernelEx(&cfg2, gemm2_kernel, b2, t, out, s, ws[i], cn[i],
                               (i == 0) ? 1 : 0, (i == 3) ? 1 : 0);
        }
    }
}